// round 3
// baseline (speedup 1.0000x reference)
#include <cuda_runtime.h>
#include <cuda_bf16.h>
#include <cstdint>

// word2vec negative-sampling loss:
//   second_emb  [200000, 128] f32
//   context_emb [200000, 128] f32
//   v_i, v_j    [131072] i32
//   negsamples  [5, 131072] i32
// out: scalar f32 = -mean_b( logsig(vi.vj) + sum_k logsig(-vi.neg_k) )

#define EMBED 128
#define NUM_NEG 5
#define TPB 256
#define WPB 8                      // warps per block
#define MAX_BLOCKS 16384           // batch / WPB for batch=131072
#define GROUPS 128

__device__ float        g_partials[MAX_BLOCKS];
__device__ float        g_group[GROUPS];
__device__ unsigned int g_gticket[GROUPS];   // zero-initialized at load
__device__ unsigned int g_fticket;           // zero-initialized at load

__device__ __forceinline__ float fast_log_sigmoid(float x) {
    // logsig(x) = min(x,0) - log(1 + exp(-|x|));  exp arg in [-inf,0] -> t in (0,1]
    return fminf(x, 0.0f) - __logf(1.0f + __expf(-fabsf(x)));
}

__device__ __forceinline__ float dot4(float4 a, float4 b) {
    return fmaf(a.x, b.x, fmaf(a.y, b.y, fmaf(a.z, b.z, a.w * b.w)));
}

__global__ void __launch_bounds__(TPB)
w2v_loss(const float* __restrict__ second_emb,
         const float* __restrict__ context_emb,
         const int* __restrict__ v_i,
         const int* __restrict__ v_j,
         const int* __restrict__ negs,
         int batch, float inv_batch,
         float* __restrict__ out)
{
    const int lane = threadIdx.x & 31;
    const int wid  = threadIdx.x >> 5;
    const int e    = blockIdx.x * WPB + wid;   // one element per warp

    float elem_loss = 0.0f;   // valid on lane 0

    if (e < batch) {
        const int ivi = __ldg(&v_i[e]);
        const int ivj = __ldg(&v_j[e]);
        int ineg[NUM_NEG];
        #pragma unroll
        for (int k = 0; k < NUM_NEG; k++)
            ineg[k] = __ldg(&negs[(size_t)k * batch + e]);

        // lane l holds float4 at offset 4l -> one coalesced 512B row read
        const float4* vi_row = reinterpret_cast<const float4*>(
            second_emb + (size_t)ivi * EMBED);
        float4 a = __ldg(&vi_row[lane]);

        // all 6 context rows issued before consumption (MLP)
        float4 r[NUM_NEG + 1];
        const float4* vj_row = reinterpret_cast<const float4*>(
            context_emb + (size_t)ivj * EMBED);
        r[0] = __ldg(&vj_row[lane]);
        #pragma unroll
        for (int k = 0; k < NUM_NEG; k++) {
            const float4* nrow = reinterpret_cast<const float4*>(
                context_emb + (size_t)ineg[k] * EMBED);
            r[k + 1] = __ldg(&nrow[lane]);
        }

        float d[NUM_NEG + 1];
        #pragma unroll
        for (int j = 0; j < NUM_NEG + 1; j++)
            d[j] = dot4(a, r[j]);

        // ---- split-butterfly reduce: stage 1 folds halves, then each
        //      half-warp finishes 3 of the 6 dots (21 shfl vs 30) ----
        #pragma unroll
        for (int j = 0; j < 6; j++)
            d[j] += __shfl_xor_sync(0xFFFFFFFFu, d[j], 16);

        const bool hi = lane >= 16;
        float v0 = hi ? d[3] : d[0];
        float v1 = hi ? d[4] : d[1];
        float v2 = hi ? d[5] : d[2];

        #pragma unroll
        for (int off = 8; off > 0; off >>= 1) {
            v0 += __shfl_xor_sync(0xFFFFFFFFu, v0, off);
            v1 += __shfl_xor_sync(0xFFFFFFFFu, v1, off);
            v2 += __shfl_xor_sync(0xFFFFFFFFu, v2, off);
        }
        // lower half lanes: v0..v2 = D0,D1,D2 ; upper half: D3,D4,D5

        // ---- distributed logsig: lanes {0,1,2,16,17,18} own one term ----
        const int sl = lane & 15;
        float x = v0;
        x = (sl == 1) ? v1 : x;
        x = (sl == 2) ? v2 : x;
        float arg = (lane == 0) ? x : -x;     // pos term only for D0
        float t = fast_log_sigmoid(arg);
        t = (sl < 3) ? t : 0.0f;

        t += __shfl_xor_sync(0xFFFFFFFFu, t, 16);
        t += __shfl_xor_sync(0xFFFFFFFFu, t, 1);
        t += __shfl_xor_sync(0xFFFFFFFFu, t, 2);
        elem_loss = t;                         // lane 0: full element loss
    }

    // ---- block reduce (deterministic) ----
    __shared__ float ws[WPB];
    if (lane == 0)
        ws[wid] = elem_loss;
    __syncthreads();

    if (threadIdx.x < 32) {
        float s = (threadIdx.x < WPB) ? ws[threadIdx.x] : 0.0f;
        #pragma unroll
        for (int off = 4; off > 0; off >>= 1)
            s += __shfl_xor_sync(0xFFFFFFFFu, s, off);
        if (threadIdx.x == 0)
            g_partials[blockIdx.x] = s;
    }

    // ---- two-level deterministic fold ----
    const int grid = gridDim.x;
    const int bpg  = (grid + GROUPS - 1) / GROUPS;       // blocks per group
    const int grp  = blockIdx.x / bpg;
    const int gbeg = grp * bpg;
    const int gsz  = min(bpg, grid - gbeg);
    const int ngroups = (grid + bpg - 1) / bpg;

    __shared__ int lastInGroup;
    if (threadIdx.x == 0) {
        __threadfence();
        unsigned int old = atomicAdd(&g_gticket[grp], 1u);
        lastInGroup = (old == (unsigned int)(gsz - 1));
        if (lastInGroup)
            g_gticket[grp] = 0;   // reset for next graph replay
    }
    __syncthreads();

    if (lastInGroup) {
        // fold this group's partials (fixed order -> deterministic)
        float s = 0.0f;
        for (int i = threadIdx.x; i < gsz; i += TPB)
            s += __ldcg(&g_partials[gbeg + i]);
        #pragma unroll
        for (int off = 16; off > 0; off >>= 1)
            s += __shfl_xor_sync(0xFFFFFFFFu, s, off);
        __shared__ float gs[WPB];
        if (lane == 0)
            gs[wid] = s;
        __syncthreads();

        __shared__ int lastAll;
        if (threadIdx.x == 0) {
            float t2 = 0.0f;
            #pragma unroll
            for (int w = 0; w < WPB; w++)
                t2 += gs[w];
            g_group[grp] = t2;
            __threadfence();
            unsigned int old2 = atomicAdd(&g_fticket, 1u);
            lastAll = (old2 == (unsigned int)(ngroups - 1));
            if (lastAll)
                g_fticket = 0;   // reset for next graph replay
        }
        __syncthreads();

        if (lastAll) {
            float f = (threadIdx.x < ngroups) ? __ldcg(&g_group[threadIdx.x]) : 0.0f;
            // reduce up to 128 values: shuffle within warp, then across 4 warps
            #pragma unroll
            for (int off = 16; off > 0; off >>= 1)
                f += __shfl_xor_sync(0xFFFFFFFFu, f, off);
            __shared__ float fs[WPB];
            if (lane == 0)
                fs[wid] = f;
            __syncthreads();
            if (threadIdx.x == 0) {
                float tot = 0.0f;
                #pragma unroll
                for (int w = 0; w < WPB; w++)
                    tot += fs[w];
                out[0] = -tot * inv_batch;
            }
        }
    }
}

extern "C" void kernel_launch(void* const* d_in, const int* in_sizes, int n_in,
                              void* d_out, int out_size)
{
    const float* second_emb  = (const float*)d_in[0];
    const float* context_emb = (const float*)d_in[1];
    const int*   v_i         = (const int*)d_in[2];
    const int*   v_j         = (const int*)d_in[3];
    const int*   negs        = (const int*)d_in[4];

    const int batch  = in_sizes[2];                 // 131072
    int blocks = (batch + WPB - 1) / WPB;           // 16384
    if (blocks > MAX_BLOCKS) blocks = MAX_BLOCKS;   // safety (not hit here)

    w2v_loss<<<blocks, TPB>>>(second_emb, context_emb, v_i, v_j, negs,
                              batch, 1.0f / (float)batch, (float*)d_out);
}

// round 4
// speedup vs baseline: 1.2878x; 1.2878x over previous
#include <cuda_runtime.h>
#include <cuda_bf16.h>
#include <cstdint>

// word2vec negative-sampling loss:
//   second_emb  [200000, 128] f32
//   context_emb [200000, 128] f32
//   v_i, v_j    [131072] i32
//   negsamples  [5, 131072] i32
// out: scalar f32 = -mean_b( logsig(vi.vj) + sum_k logsig(-vi.neg_k) )
//
// Two kernels, NO __threadfence anywhere: gpu-scope fence emits CCTL.IVALL
// on sm_103a which flushes L1D for all resident blocks (measured regression
// R2/R3). The kernel boundary provides the ordering for free.

#define EMBED 128
#define NUM_NEG 5
#define TPB 256
#define WPB 8                       // warps per block
#define NPART 16384                 // batch / WPB

__device__ float g_partials[NPART];

__device__ __forceinline__ float fast_log_sigmoid(float x) {
    // logsig(x) = min(x,0) - log(1 + exp(-|x|))
    return fminf(x, 0.0f) - __logf(1.0f + __expf(-fabsf(x)));
}

__device__ __forceinline__ float dot4(float4 a, float4 b) {
    return fmaf(a.x, b.x, fmaf(a.y, b.y, fmaf(a.z, b.z, a.w * b.w)));
}

__global__ void __launch_bounds__(TPB)
w2v_main(const float* __restrict__ second_emb,
         const float* __restrict__ context_emb,
         const int* __restrict__ v_i,
         const int* __restrict__ v_j,
         const int* __restrict__ negs,
         int batch)
{
    const int lane = threadIdx.x & 31;
    const int wid  = threadIdx.x >> 5;
    const int e    = blockIdx.x * WPB + wid;    // one element per warp

    float elem_loss = 0.0f;   // valid on lane 0

    if (e < batch) {
        // uniform (broadcast) index loads
        const int ivi = __ldg(&v_i[e]);
        const int ivj = __ldg(&v_j[e]);
        int ineg[NUM_NEG];
        #pragma unroll
        for (int k = 0; k < NUM_NEG; k++)
            ineg[k] = __ldg(&negs[k * batch + e]);

        // 32-bit row offsets (200000*128 < 2^31) -> cheaper addressing
        const float4* vi_row = reinterpret_cast<const float4*>(
            second_emb + (unsigned)ivi * EMBED);
        float4 a = __ldg(&vi_row[lane]);

        // issue all 6 context-row loads before consuming (MLP)
        float4 r[NUM_NEG + 1];
        const float4* vj_row = reinterpret_cast<const float4*>(
            context_emb + (unsigned)ivj * EMBED);
        r[0] = __ldg(&vj_row[lane]);
        #pragma unroll
        for (int k = 0; k < NUM_NEG; k++) {
            const float4* nrow = reinterpret_cast<const float4*>(
                context_emb + (unsigned)ineg[k] * EMBED);
            r[k + 1] = __ldg(&nrow[lane]);
        }

        float d[NUM_NEG + 1];
        #pragma unroll
        for (int j = 0; j < NUM_NEG + 1; j++)
            d[j] = dot4(a, r[j]);

        // split-butterfly: fold halves once, then each half-warp finishes
        // 3 of the 6 dot reductions (21 shuffles instead of 30)
        #pragma unroll
        for (int j = 0; j < 6; j++)
            d[j] += __shfl_xor_sync(0xFFFFFFFFu, d[j], 16);

        const bool hi = lane >= 16;
        float v0 = hi ? d[3] : d[0];
        float v1 = hi ? d[4] : d[1];
        float v2 = hi ? d[5] : d[2];

        #pragma unroll
        for (int off = 8; off > 0; off >>= 1) {
            v0 += __shfl_xor_sync(0xFFFFFFFFu, v0, off);
            v1 += __shfl_xor_sync(0xFFFFFFFFu, v1, off);
            v2 += __shfl_xor_sync(0xFFFFFFFFu, v2, off);
        }
        // low half lanes hold D0,D1,D2; high half D3,D4,D5 (replicated)

        // distributed logsig: lanes {0,1,2,16,17,18} each own one term
        const int sl = lane & 15;
        float x = v0;
        x = (sl == 1) ? v1 : x;
        x = (sl == 2) ? v2 : x;
        float arg = (lane == 0) ? x : -x;      // positive term only for D0
        float t = fast_log_sigmoid(arg);
        t = (sl < 3) ? t : 0.0f;

        t += __shfl_xor_sync(0xFFFFFFFFu, t, 16);
        t += __shfl_xor_sync(0xFFFFFFFFu, t, 1);
        t += __shfl_xor_sync(0xFFFFFFFFu, t, 2);
        elem_loss = t;                          // lane 0 holds element loss
    }

    // block reduce (deterministic), one partial per block
    __shared__ float ws[WPB];
    if (lane == 0)
        ws[wid] = elem_loss;
    __syncthreads();

    if (threadIdx.x < 32) {
        float s = (threadIdx.x < WPB) ? ws[threadIdx.x] : 0.0f;
        #pragma unroll
        for (int off = 4; off > 0; off >>= 1)
            s += __shfl_xor_sync(0xFFFFFFFFu, s, off);
        if (threadIdx.x == 0)
            g_partials[blockIdx.x] = s;
    }
}

__global__ void __launch_bounds__(1024)
w2v_reduce(float* __restrict__ out, float inv_batch)
{
    // 16384 partials = 4096 float4; 1024 threads x 4 independent float4 each
    const float4* p = reinterpret_cast<const float4*>(g_partials);
    const int tid = threadIdx.x;

    float4 s4 = make_float4(0.f, 0.f, 0.f, 0.f);
    #pragma unroll
    for (int i = 0; i < 4; i++) {
        float4 v = __ldg(&p[tid + i * 1024]);
        s4.x += v.x; s4.y += v.y; s4.z += v.z; s4.w += v.w;
    }
    float s = (s4.x + s4.y) + (s4.z + s4.w);

    #pragma unroll
    for (int off = 16; off > 0; off >>= 1)
        s += __shfl_xor_sync(0xFFFFFFFFu, s, off);

    __shared__ float sh[32];
    if ((tid & 31) == 0)
        sh[tid >> 5] = s;
    __syncthreads();

    if (tid < 32) {
        float t = sh[tid];
        #pragma unroll
        for (int off = 16; off > 0; off >>= 1)
            t += __shfl_xor_sync(0xFFFFFFFFu, t, off);
        if (tid == 0)
            out[0] = -t * inv_batch;
    }
}

extern "C" void kernel_launch(void* const* d_in, const int* in_sizes, int n_in,
                              void* d_out, int out_size)
{
    const float* second_emb  = (const float*)d_in[0];
    const float* context_emb = (const float*)d_in[1];
    const int*   v_i         = (const int*)d_in[2];
    const int*   v_j         = (const int*)d_in[3];
    const int*   negs        = (const int*)d_in[4];

    const int batch  = in_sizes[2];                 // 131072
    const int blocks = (batch + WPB - 1) / WPB;     // 16384

    w2v_main<<<blocks, TPB>>>(second_emb, context_emb, v_i, v_j, negs, batch);
    w2v_reduce<<<1, 1024>>>((float*)d_out, 1.0f / (float)batch);
}

// round 5
// speedup vs baseline: 1.3851x; 1.0756x over previous
#include <cuda_runtime.h>
#include <cuda_bf16.h>
#include <cstdint>

// word2vec negative-sampling loss:
//   second_emb  [200000, 128] f32
//   context_emb [200000, 128] f32
//   v_i, v_j    [131072] i32
//   negsamples  [5, 131072] i32
// out: scalar f32 = -mean_b( logsig(vi.vj) + sum_k logsig(-vi.neg_k) )
//
// Two kernels, NO __threadfence anywhere (gpu-scope fence = CCTL.IVALL =
// full L1D flush on sm_103a; measured -8..-15us regression in R2/R3).

#define EMBED 128
#define NUM_NEG 5
#define TPB 512
#define WPB 16                      // warps per block
#define NPART 8192                  // batch / WPB for batch=131072

__device__ float g_partials[NPART];

__device__ __forceinline__ float fast_log_sigmoid(float x) {
    // logsig(x) = min(x,0) - log(1 + exp(-|x|))
    return fminf(x, 0.0f) - __logf(1.0f + __expf(-fabsf(x)));
}

__device__ __forceinline__ float dot4(float4 a, float4 b) {
    return fmaf(a.x, b.x, fmaf(a.y, b.y, fmaf(a.z, b.z, a.w * b.w)));
}

__global__ void __launch_bounds__(TPB)
w2v_main(const float* __restrict__ second_emb,
         const float* __restrict__ context_emb,
         const int* __restrict__ v_i,
         const int* __restrict__ v_j,
         const int* __restrict__ negs,
         int batch)
{
    const int lane = threadIdx.x & 31;
    const int wid  = threadIdx.x >> 5;
    const int e    = blockIdx.x * WPB + wid;    // one element per warp

    float elem_loss = 0.0f;   // valid on lane 0

    if (e < batch) {
        // ---- lane-distributed index gather: ONE LDG for all 7 indices ----
        // lane 0 -> v_i[e], lane 1 -> v_j[e], lanes 2..6 -> negs[k][e]
        int myidx = 0;
        if (lane < 7) {
            const int* p;
            if (lane == 0)      p = v_i + e;
            else if (lane == 1) p = v_j + e;
            else                p = negs + (lane - 2) * batch + e;
            myidx = __ldg(p);
        }
        const int ivi = __shfl_sync(0xFFFFFFFFu, myidx, 0);
        const int ivj = __shfl_sync(0xFFFFFFFFu, myidx, 1);
        int ineg[NUM_NEG];
        #pragma unroll
        for (int k = 0; k < NUM_NEG; k++)
            ineg[k] = __shfl_sync(0xFFFFFFFFu, myidx, k + 2);

        // 32-bit row offsets (200000*128 < 2^31)
        const float4* vi_row = reinterpret_cast<const float4*>(
            second_emb + (unsigned)ivi * EMBED);
        float4 a = __ldg(&vi_row[lane]);

        // all 6 context rows issued before consumption (MLP)
        float4 r[NUM_NEG + 1];
        const float4* vj_row = reinterpret_cast<const float4*>(
            context_emb + (unsigned)ivj * EMBED);
        r[0] = __ldg(&vj_row[lane]);
        #pragma unroll
        for (int k = 0; k < NUM_NEG; k++) {
            const float4* nrow = reinterpret_cast<const float4*>(
                context_emb + (unsigned)ineg[k] * EMBED);
            r[k + 1] = __ldg(&nrow[lane]);
        }

        float d[NUM_NEG + 1];
        #pragma unroll
        for (int j = 0; j < NUM_NEG + 1; j++)
            d[j] = dot4(a, r[j]);

        // split-butterfly: fold halves once, then each half-warp finishes
        // 3 of the 6 dot reductions (21 shuffles instead of 30)
        #pragma unroll
        for (int j = 0; j < 6; j++)
            d[j] += __shfl_xor_sync(0xFFFFFFFFu, d[j], 16);

        const bool hi = lane >= 16;
        float v0 = hi ? d[3] : d[0];
        float v1 = hi ? d[4] : d[1];
        float v2 = hi ? d[5] : d[2];

        #pragma unroll
        for (int off = 8; off > 0; off >>= 1) {
            v0 += __shfl_xor_sync(0xFFFFFFFFu, v0, off);
            v1 += __shfl_xor_sync(0xFFFFFFFFu, v1, off);
            v2 += __shfl_xor_sync(0xFFFFFFFFu, v2, off);
        }
        // low half lanes hold D0,D1,D2; high half D3,D4,D5 (replicated)

        // distributed logsig: lanes {0,1,2,16,17,18} each own one term
        const int sl = lane & 15;
        float x = v0;
        x = (sl == 1) ? v1 : x;
        x = (sl == 2) ? v2 : x;
        float arg = (lane == 0) ? x : -x;      // positive term only for D0
        float t = fast_log_sigmoid(arg);
        t = (sl < 3) ? t : 0.0f;

        t += __shfl_xor_sync(0xFFFFFFFFu, t, 16);
        t += __shfl_xor_sync(0xFFFFFFFFu, t, 1);
        t += __shfl_xor_sync(0xFFFFFFFFu, t, 2);
        elem_loss = t;                          // lane 0 holds element loss
    }

    // block reduce (deterministic): 16 warp values -> 1 partial
    __shared__ float ws[WPB];
    if (lane == 0)
        ws[wid] = elem_loss;
    __syncthreads();

    if (threadIdx.x < 32) {
        float s = (threadIdx.x < WPB) ? ws[threadIdx.x] : 0.0f;
        #pragma unroll
        for (int off = 8; off > 0; off >>= 1)
            s += __shfl_xor_sync(0xFFFFFFFFu, s, off);
        if (threadIdx.x == 0)
            g_partials[blockIdx.x] = s;
    }
}

__global__ void __launch_bounds__(1024)
w2v_reduce(float* __restrict__ out, float inv_batch)
{
    // 8192 partials = 2048 float4; 1024 threads x 2 independent float4 each
    const float4* p = reinterpret_cast<const float4*>(g_partials);
    const int tid = threadIdx.x;

    float4 u = __ldg(&p[tid]);
    float4 v = __ldg(&p[tid + 1024]);
    float s = ((u.x + u.y) + (u.z + u.w)) + ((v.x + v.y) + (v.z + v.w));

    #pragma unroll
    for (int off = 16; off > 0; off >>= 1)
        s += __shfl_xor_sync(0xFFFFFFFFu, s, off);

    __shared__ float sh[32];
    if ((tid & 31) == 0)
        sh[tid >> 5] = s;
    __syncthreads();

    if (tid < 32) {
        float t = sh[tid];
        #pragma unroll
        for (int off = 16; off > 0; off >>= 1)
            t += __shfl_xor_sync(0xFFFFFFFFu, t, off);
        if (tid == 0)
            out[0] = -t * inv_batch;
    }
}

extern "C" void kernel_launch(void* const* d_in, const int* in_sizes, int n_in,
                              void* d_out, int out_size)
{
    const float* second_emb  = (const float*)d_in[0];
    const float* context_emb = (const float*)d_in[1];
    const int*   v_i         = (const int*)d_in[2];
    const int*   v_j         = (const int*)d_in[3];
    const int*   negs        = (const int*)d_in[4];

    const int batch  = in_sizes[2];                 // 131072
    const int blocks = (batch + WPB - 1) / WPB;     // 8192

    w2v_main<<<blocks, TPB>>>(second_emb, context_emb, v_i, v_j, negs, batch);
    w2v_reduce<<<1, 1024>>>((float*)d_out, 1.0f / (float)batch);
}